// round 1
// baseline (speedup 1.0000x reference)
#include <cuda_runtime.h>

#define Bq 8
#define Sq 1024
#define Dm 1024
#define NH 16
#define DH 64
#define NEGV (-1e9f)
#define SROW 1028   // padded score row stride (floats): (lane/4)*1028 %32 = 4*(lane/4) -> conflict-free frags

// ---- scratch (device globals: allocation-free rule) ----
__device__ float g_Q[(size_t)Bq*NH*Sq*DH];
__device__ float g_K[(size_t)Bq*NH*Sq*DH];
__device__ float g_V[(size_t)Bq*NH*Sq*DH];
__device__ float g_heads[(size_t)Bq*Sq*Dm];

// ---- tf32 helpers ----
__device__ __forceinline__ unsigned f2tf(float f) {
    unsigned r;
    asm("cvt.rna.tf32.f32 %0, %1;" : "=r"(r) : "f"(f));
    return r;
}
__device__ __forceinline__ void mma_tf32(float c[4],
                                         unsigned a0, unsigned a1, unsigned a2, unsigned a3,
                                         unsigned b0, unsigned b1) {
    asm volatile(
        "mma.sync.aligned.m16n8k8.row.col.f32.tf32.tf32.f32 "
        "{%0,%1,%2,%3}, {%4,%5,%6,%7}, {%8,%9}, {%0,%1,%2,%3};"
        : "+f"(c[0]), "+f"(c[1]), "+f"(c[2]), "+f"(c[3])
        : "r"(a0), "r"(a1), "r"(a2), "r"(a3), "r"(b0), "r"(b1));
}

// ============================================================================
// K1: fused QKV projection. Per head h: C[8192x64] = Hh[8192x64] @ W[h]^T + b
// block: 256 thr, tile 128 rows x 64 cols. grid (64, NH)
// ============================================================================
__global__ void __launch_bounds__(256) qkv_kernel(
    const float* __restrict__ H,
    const float* __restrict__ Wq, const float* __restrict__ bq,
    const float* __restrict__ Wk, const float* __restrict__ bk,
    const float* __restrict__ Wv, const float* __restrict__ bv)
{
    extern __shared__ float sm[];
    float* Hs = sm;              // 128 x 68
    float* Ws = sm + 128 * 68;   // 64 x 68

    const int tid  = threadIdx.x;
    const int lane = tid & 31;
    const int warp = tid >> 5;
    const int warpM = warp >> 1;   // 0..3 -> 32 rows each
    const int warpN = warp & 1;    // 0..1 -> 32 cols each
    const int h    = blockIdx.y;
    const int row0 = blockIdx.x * 128;   // global row in [0, B*S)
    const int b    = row0 >> 10;
    const int s    = row0 & 1023;

    // load H slice for this head: 128 x 64
    for (int i = tid; i < 128 * 16; i += 256) {
        int r = i >> 4, q = i & 15;
        float4 v = *(const float4*)&H[(size_t)(row0 + r) * Dm + h * DH + q * 4];
        float* dst = &Hs[r * 68 + q * 4];
        dst[0] = v.x; dst[1] = v.y; dst[2] = v.z; dst[3] = v.w;
    }

    const float* Wt[3] = {Wq, Wk, Wv};
    const float* bt[3] = {bq, bk, bv};
    float*       Ot[3] = {g_Q, g_K, g_V};

    for (int wsel = 0; wsel < 3; wsel++) {
        __syncthreads();   // Hs visible (iter 0) / Ws reuse safe (iters 1,2)
        const float* W = Wt[wsel] + h * DH * DH;
        for (int i = tid; i < 64 * 16; i += 256) {
            int r = i >> 4, q = i & 15;
            float4 v = *(const float4*)&W[r * DH + q * 4];
            float* dst = &Ws[r * 68 + q * 4];
            dst[0] = v.x; dst[1] = v.y; dst[2] = v.z; dst[3] = v.w;
        }
        __syncthreads();

        float c[2][4][4];
        #pragma unroll
        for (int mi = 0; mi < 2; mi++)
            #pragma unroll
            for (int ni = 0; ni < 4; ni++)
                #pragma unroll
                for (int q = 0; q < 4; q++) c[mi][ni][q] = 0.f;

        #pragma unroll
        for (int k0 = 0; k0 < 64; k0 += 8) {
            unsigned a[2][4], bb[4][2];
            #pragma unroll
            for (int mi = 0; mi < 2; mi++) {
                int rb = warpM * 32 + mi * 16 + (lane >> 2);
                a[mi][0] = f2tf(Hs[rb * 68 + k0 + (lane & 3)]);
                a[mi][1] = f2tf(Hs[(rb + 8) * 68 + k0 + (lane & 3)]);
                a[mi][2] = f2tf(Hs[rb * 68 + k0 + 4 + (lane & 3)]);
                a[mi][3] = f2tf(Hs[(rb + 8) * 68 + k0 + 4 + (lane & 3)]);
            }
            #pragma unroll
            for (int ni = 0; ni < 4; ni++) {
                int nb = warpN * 32 + ni * 8 + (lane >> 2);
                bb[ni][0] = f2tf(Ws[nb * 68 + k0 + (lane & 3)]);
                bb[ni][1] = f2tf(Ws[nb * 68 + k0 + 4 + (lane & 3)]);
            }
            #pragma unroll
            for (int mi = 0; mi < 2; mi++)
                #pragma unroll
                for (int ni = 0; ni < 4; ni++)
                    mma_tf32(c[mi][ni], a[mi][0], a[mi][1], a[mi][2], a[mi][3],
                             bb[ni][0], bb[ni][1]);
        }

        float* O = Ot[wsel] + ((size_t)(b * NH + h) * Sq + s) * DH;
        const float* bias = bt[wsel] + h * DH;
        #pragma unroll
        for (int mi = 0; mi < 2; mi++) {
            #pragma unroll
            for (int ni = 0; ni < 4; ni++) {
                int r  = warpM * 32 + mi * 16 + (lane >> 2);
                int cN = warpN * 32 + ni * 8 + (lane & 3) * 2;
                float b0v = bias[cN], b1v = bias[cN + 1];
                O[(size_t)r * DH + cN]           = c[mi][ni][0] + b0v;
                O[(size_t)r * DH + cN + 1]       = c[mi][ni][1] + b1v;
                O[(size_t)(r + 8) * DH + cN]     = c[mi][ni][2] + b0v;
                O[(size_t)(r + 8) * DH + cN + 1] = c[mi][ni][3] + b1v;
            }
        }
    }
}

// ============================================================================
// K2: attention. block = (b, h, 32 query rows). Scores kept in smem (32x1028),
// masked softmax in-place, A written once, then P@V fused with renorm epilogue.
// 256 thr / 8 warps. grid (32, B, NH).
// ============================================================================
__global__ void __launch_bounds__(256) attn_kernel(
    const int* __restrict__ mask, float* __restrict__ Aout)
{
    extern __shared__ float sm[];
    float* ps   = sm;                       // 32 x 1028 scores
    float* Qs   = sm + 32 * SROW;           // 32 x 68
    float* KVs  = Qs + 32 * 68;             // 128 x 68 (K tile, then V tiles)
    float* rinv = KVs + 128 * 68;           // 32

    const int tid = threadIdx.x, lane = tid & 31, warp = tid >> 5;
    const int h = blockIdx.z, b = blockIdx.y, s0 = blockIdx.x * 32;

    const float* Qg = g_Q + ((size_t)(b * NH + h) * Sq + s0) * DH;
    const float* Kg = g_K + (size_t)(b * NH + h) * Sq * DH;
    const float* Vg = g_V + (size_t)(b * NH + h) * Sq * DH;

    for (int i = tid; i < 32 * 16; i += 256) {
        int r = i >> 4, q = i & 15;
        float4 v = *(const float4*)&Qg[(size_t)r * DH + q * 4];
        float* dst = &Qs[r * 68 + q * 4];
        dst[0] = v.x; dst[1] = v.y; dst[2] = v.z; dst[3] = v.w;
    }

    const int warpM = warp >> 2;   // 0..1 -> 16 rows
    const int warpN = warp & 3;    // 0..3 -> 32 cols (of 128-wide K tile)

    // ---- Phase A: scores = Q K^T / 8 into smem ----
    for (int kt = 0; kt < 8; kt++) {
        __syncthreads();
        for (int i = tid; i < 128 * 16; i += 256) {
            int r = i >> 4, q = i & 15;
            float4 v = *(const float4*)&Kg[(size_t)(kt * 128 + r) * DH + q * 4];
            float* dst = &KVs[r * 68 + q * 4];
            dst[0] = v.x; dst[1] = v.y; dst[2] = v.z; dst[3] = v.w;
        }
        __syncthreads();

        float c[4][4];
        #pragma unroll
        for (int ni = 0; ni < 4; ni++)
            #pragma unroll
            for (int q = 0; q < 4; q++) c[ni][q] = 0.f;

        #pragma unroll
        for (int k0 = 0; k0 < 64; k0 += 8) {
            int rb = warpM * 16 + (lane >> 2);
            unsigned a0 = f2tf(Qs[rb * 68 + k0 + (lane & 3)]);
            unsigned a1 = f2tf(Qs[(rb + 8) * 68 + k0 + (lane & 3)]);
            unsigned a2 = f2tf(Qs[rb * 68 + k0 + 4 + (lane & 3)]);
            unsigned a3 = f2tf(Qs[(rb + 8) * 68 + k0 + 4 + (lane & 3)]);
            #pragma unroll
            for (int ni = 0; ni < 4; ni++) {
                int nb = warpN * 32 + ni * 8 + (lane >> 2);
                unsigned b0 = f2tf(KVs[nb * 68 + k0 + (lane & 3)]);
                unsigned b1 = f2tf(KVs[nb * 68 + k0 + 4 + (lane & 3)]);
                mma_tf32(c[ni], a0, a1, a2, a3, b0, b1);
            }
        }
        int r = warpM * 16 + (lane >> 2);
        #pragma unroll
        for (int ni = 0; ni < 4; ni++) {
            int cN = kt * 128 + warpN * 32 + ni * 8 + (lane & 3) * 2;
            ps[r * SROW + cN]           = c[ni][0] * 0.125f;
            ps[r * SROW + cN + 1]       = c[ni][1] * 0.125f;
            ps[(r + 8) * SROW + cN]     = c[ni][2] * 0.125f;
            ps[(r + 8) * SROW + cN + 1] = c[ni][3] * 0.125f;
        }
    }
    __syncthreads();

    // ---- Phase A2: mask + softmax (warp w owns rows 4w..4w+3) ----
    {
        const int* mbase = mask + ((size_t)b * Sq + s0) * Sq;
        #pragma unroll
        for (int ri = 0; ri < 4; ri++) {
            int r = warp * 4 + ri;
            const int* mrow = mbase + (size_t)r * Sq;
            float mx = NEGV;
            for (int t = 0; t < 32; t++) {
                int j = lane + 32 * t;
                float sv = ps[r * SROW + j];
                if (mrow[j] == 0) sv = NEGV;
                ps[r * SROW + j] = sv;
                mx = fmaxf(mx, sv);
            }
            #pragma unroll
            for (int o = 16; o; o >>= 1) mx = fmaxf(mx, __shfl_xor_sync(~0u, mx, o));
            float sum = 0.f;
            for (int t = 0; t < 32; t++) {
                int j = lane + 32 * t;
                float e = __expf(ps[r * SROW + j] - mx);
                ps[r * SROW + j] = e;     // keep unnormalized exp for P@V
                sum += e;
            }
            #pragma unroll
            for (int o = 16; o; o >>= 1) sum += __shfl_xor_sync(~0u, sum, o);
            float inv = 1.0f / sum;
            if (lane == 0) rinv[r] = inv;
            float* Ar = Aout + (((size_t)h * Bq + b) * Sq + s0 + r) * Sq;
            for (int t = 0; t < 32; t++) {
                int j = lane + 32 * t;
                Ar[j] = ps[r * SROW + j] * inv;
            }
        }
    }
    __syncthreads();

    // ---- Phase B: heads(32x64) = P(32x1024) @ V(1024x64), scaled by rinv ----
    float c[2][4];
    #pragma unroll
    for (int ni = 0; ni < 2; ni++)
        #pragma unroll
        for (int q = 0; q < 4; q++) c[ni][q] = 0.f;

    for (int kt = 0; kt < 8; kt++) {
        __syncthreads();
        for (int i = tid; i < 128 * 16; i += 256) {
            int r = i >> 4, q = i & 15;
            float4 v = *(const float4*)&Vg[(size_t)(kt * 128 + r) * DH + q * 4];
            float* dst = &KVs[r * 68 + q * 4];
            dst[0] = v.x; dst[1] = v.y; dst[2] = v.z; dst[3] = v.w;
        }
        __syncthreads();

        #pragma unroll
        for (int k0 = 0; k0 < 128; k0 += 8) {
            int kk = kt * 128 + k0;
            int rb = warpM * 16 + (lane >> 2);
            unsigned a0 = f2tf(ps[rb * SROW + kk + (lane & 3)]);
            unsigned a1 = f2tf(ps[(rb + 8) * SROW + kk + (lane & 3)]);
            unsigned a2 = f2tf(ps[rb * SROW + kk + 4 + (lane & 3)]);
            unsigned a3 = f2tf(ps[(rb + 8) * SROW + kk + 4 + (lane & 3)]);
            #pragma unroll
            for (int ni = 0; ni < 2; ni++) {
                int nb = warpN * 16 + ni * 8 + (lane >> 2);
                unsigned b0 = f2tf(KVs[(k0 + (lane & 3)) * 68 + nb]);
                unsigned b1 = f2tf(KVs[(k0 + 4 + (lane & 3)) * 68 + nb]);
                mma_tf32(c[ni], a0, a1, a2, a3, b0, b1);
            }
        }
    }

    {
        int r = warpM * 16 + (lane >> 2);
        float i0 = rinv[r], i1 = rinv[r + 8];
        size_t base = ((size_t)(b * Sq + s0)) * Dm + h * DH;
        #pragma unroll
        for (int ni = 0; ni < 2; ni++) {
            int cN = warpN * 16 + ni * 8 + (lane & 3) * 2;
            g_heads[base + (size_t)r * Dm + cN]           = c[ni][0] * i0;
            g_heads[base + (size_t)r * Dm + cN + 1]       = c[ni][1] * i0;
            g_heads[base + (size_t)(r + 8) * Dm + cN]     = c[ni][2] * i1;
            g_heads[base + (size_t)(r + 8) * Dm + cN + 1] = c[ni][3] * i1;
        }
    }
}

// ============================================================================
// K3: output = heads(8192x1024) @ Wo^T(1024x1024) + bo. tile 128x64, 256 thr.
// grid (64, 16)
// ============================================================================
__global__ void __launch_bounds__(256) out_kernel(
    const float* __restrict__ Wo, const float* __restrict__ bo,
    float* __restrict__ out)
{
    extern __shared__ float sm[];
    float* As = sm;              // 128 x 68
    float* Bs = sm + 128 * 68;   // 64 x 68

    const int tid = threadIdx.x, lane = tid & 31, warp = tid >> 5;
    const int warpM = warp >> 1, warpN = warp & 1;
    const int r0 = blockIdx.x * 128, n0 = blockIdx.y * 64;

    float c[2][4][4];
    #pragma unroll
    for (int mi = 0; mi < 2; mi++)
        #pragma unroll
        for (int ni = 0; ni < 4; ni++)
            #pragma unroll
            for (int q = 0; q < 4; q++) c[mi][ni][q] = 0.f;

    for (int kt = 0; kt < 16; kt++) {
        __syncthreads();
        for (int i = tid; i < 128 * 16; i += 256) {
            int r = i >> 4, q = i & 15;
            float4 v = *(const float4*)&g_heads[(size_t)(r0 + r) * Dm + kt * 64 + q * 4];
            float* dst = &As[r * 68 + q * 4];
            dst[0] = v.x; dst[1] = v.y; dst[2] = v.z; dst[3] = v.w;
        }
        for (int i = tid; i < 64 * 16; i += 256) {
            int r = i >> 4, q = i & 15;
            float4 v = *(const float4*)&Wo[(size_t)(n0 + r) * Dm + kt * 64 + q * 4];
            float* dst = &Bs[r * 68 + q * 4];
            dst[0] = v.x; dst[1] = v.y; dst[2] = v.z; dst[3] = v.w;
        }
        __syncthreads();

        #pragma unroll
        for (int k0 = 0; k0 < 64; k0 += 8) {
            unsigned a[2][4], bb[4][2];
            #pragma unroll
            for (int mi = 0; mi < 2; mi++) {
                int rb = warpM * 32 + mi * 16 + (lane >> 2);
                a[mi][0] = f2tf(As[rb * 68 + k0 + (lane & 3)]);
                a[mi][1] = f2tf(As[(rb + 8) * 68 + k0 + (lane & 3)]);
                a[mi][2] = f2tf(As[rb * 68 + k0 + 4 + (lane & 3)]);
                a[mi][3] = f2tf(As[(rb + 8) * 68 + k0 + 4 + (lane & 3)]);
            }
            #pragma unroll
            for (int ni = 0; ni < 4; ni++) {
                int nb = warpN * 32 + ni * 8 + (lane >> 2);
                bb[ni][0] = f2tf(Bs[nb * 68 + k0 + (lane & 3)]);
                bb[ni][1] = f2tf(Bs[nb * 68 + k0 + 4 + (lane & 3)]);
            }
            #pragma unroll
            for (int mi = 0; mi < 2; mi++)
                #pragma unroll
                for (int ni = 0; ni < 4; ni++)
                    mma_tf32(c[mi][ni], a[mi][0], a[mi][1], a[mi][2], a[mi][3],
                             bb[ni][0], bb[ni][1]);
        }
    }

    #pragma unroll
    for (int mi = 0; mi < 2; mi++) {
        #pragma unroll
        for (int ni = 0; ni < 4; ni++) {
            int r  = r0 + warpM * 32 + mi * 16 + (lane >> 2);
            int cN = n0 + warpN * 32 + ni * 8 + (lane & 3) * 2;
            float b0v = bo[cN], b1v = bo[cN + 1];
            out[(size_t)r * Dm + cN]           = c[mi][ni][0] + b0v;
            out[(size_t)r * Dm + cN + 1]       = c[mi][ni][1] + b1v;
            out[(size_t)(r + 8) * Dm + cN]     = c[mi][ni][2] + b0v;
            out[(size_t)(r + 8) * Dm + cN + 1] = c[mi][ni][3] + b1v;
        }
    }
}

// ============================================================================
extern "C" void kernel_launch(void* const* d_in, const int* in_sizes, int n_in,
                              void* d_out, int out_size)
{
    const float* H    = (const float*)d_in[0];
    const int*   mask = (const int*)  d_in[1];
    const float* Wq   = (const float*)d_in[2];
    const float* bq   = (const float*)d_in[3];
    const float* Wk   = (const float*)d_in[4];
    const float* bk   = (const float*)d_in[5];
    const float* Wv   = (const float*)d_in[6];
    const float* bv   = (const float*)d_in[7];
    const float* Wo   = (const float*)d_in[8];
    const float* bo   = (const float*)d_in[9];

    float* out  = (float*)d_out;
    float* Aout = out + (size_t)Bq * Sq * Dm;

    const int smem1 = (128 + 64) * 68 * sizeof(float);                       // 52224
    const int smem2 = (32 * SROW + 32 * 68 + 128 * 68 + 32) * sizeof(float); // 175232
    const int smem3 = (128 + 64) * 68 * sizeof(float);                       // 52224

    cudaFuncSetAttribute(qkv_kernel,  cudaFuncAttributeMaxDynamicSharedMemorySize, smem1);
    cudaFuncSetAttribute(attn_kernel, cudaFuncAttributeMaxDynamicSharedMemorySize, smem2);
    cudaFuncSetAttribute(out_kernel,  cudaFuncAttributeMaxDynamicSharedMemorySize, smem3);

    qkv_kernel<<<dim3(64, NH), 256, smem1>>>(H, Wq, bq, Wk, bk, Wv, bv);
    attn_kernel<<<dim3(32, Bq, NH), 256, smem2>>>(mask, Aout);
    out_kernel<<<dim3(64, 16), 256, smem3>>>(Wo, bo, out);
}

// round 2
// speedup vs baseline: 1.1218x; 1.1218x over previous
#include <cuda_runtime.h>
#include <cuda_fp16.h>

#define Bq 8
#define Sq 1024
#define Dm 1024
#define NH 16
#define DH 64
#define NEGV (-1e9f)

#define PS_STRIDE 1032   // f32 score row stride
#define P_STRIDE  1032   // half P row stride (2064B, 16B aligned, bank+4/row)
#define TS 72            // half tile row stride (144B: bank 4r+c, conflict-free)

// ---- scratch (device globals: allocation-free rule) ----
__device__ __half g_Q[(size_t)Bq*NH*Sq*DH];
__device__ __half g_K[(size_t)Bq*NH*Sq*DH];
__device__ float  g_V[(size_t)Bq*NH*Sq*DH];
__device__ float  g_heads[(size_t)Bq*Sq*Dm];

// ---- helpers ----
__device__ __forceinline__ unsigned f2tf(float f) {
    unsigned r;
    asm("cvt.rna.tf32.f32 %0, %1;" : "=r"(r) : "f"(f));
    return r;
}
__device__ __forceinline__ void mma_tf32(float c[4],
                                         unsigned a0, unsigned a1, unsigned a2, unsigned a3,
                                         unsigned b0, unsigned b1) {
    asm volatile(
        "mma.sync.aligned.m16n8k8.row.col.f32.tf32.tf32.f32 "
        "{%0,%1,%2,%3}, {%4,%5,%6,%7}, {%8,%9}, {%0,%1,%2,%3};"
        : "+f"(c[0]), "+f"(c[1]), "+f"(c[2]), "+f"(c[3])
        : "r"(a0), "r"(a1), "r"(a2), "r"(a3), "r"(b0), "r"(b1));
}
__device__ __forceinline__ void mma_f16(float c[4], const unsigned a[4],
                                        unsigned b0, unsigned b1) {
    asm volatile(
        "mma.sync.aligned.m16n8k16.row.col.f32.f16.f16.f32 "
        "{%0,%1,%2,%3}, {%4,%5,%6,%7}, {%8,%9}, {%0,%1,%2,%3};"
        : "+f"(c[0]), "+f"(c[1]), "+f"(c[2]), "+f"(c[3])
        : "r"(a[0]), "r"(a[1]), "r"(a[2]), "r"(a[3]), "r"(b0), "r"(b1));
}
__device__ __forceinline__ unsigned sptr(const void* p) {
    return (unsigned)__cvta_generic_to_shared(p);
}
__device__ __forceinline__ void ldm_x4(unsigned r[4], unsigned addr) {
    asm volatile("ldmatrix.sync.aligned.m8n8.x4.shared.b16 {%0,%1,%2,%3}, [%4];"
                 : "=r"(r[0]), "=r"(r[1]), "=r"(r[2]), "=r"(r[3]) : "r"(addr));
}
__device__ __forceinline__ void ldm_x4_t(unsigned r[4], unsigned addr) {
    asm volatile("ldmatrix.sync.aligned.m8n8.x4.trans.shared.b16 {%0,%1,%2,%3}, [%4];"
                 : "=r"(r[0]), "=r"(r[1]), "=r"(r[2]), "=r"(r[3]) : "r"(addr));
}

// ============================================================================
// K1: fused QKV projection (tf32 compute from f32 inputs, proven).
// Q,K stored half; V stored float (protects output-path precision).
// grid (64, NH), 256 thr.
// ============================================================================
__global__ void __launch_bounds__(256) qkv_kernel(
    const float* __restrict__ H,
    const float* __restrict__ Wq, const float* __restrict__ bq,
    const float* __restrict__ Wk, const float* __restrict__ bk,
    const float* __restrict__ Wv, const float* __restrict__ bv)
{
    extern __shared__ float sm[];
    float* Hs = sm;              // 128 x 68
    float* Ws = sm + 128 * 68;   // 64 x 68

    const int tid  = threadIdx.x;
    const int lane = tid & 31;
    const int warp = tid >> 5;
    const int warpM = warp >> 1;
    const int warpN = warp & 1;
    const int h    = blockIdx.y;
    const int row0 = blockIdx.x * 128;
    const int b    = row0 >> 10;
    const int s    = row0 & 1023;

    for (int i = tid; i < 128 * 16; i += 256) {
        int r = i >> 4, q = i & 15;
        float4 v = *(const float4*)&H[(size_t)(row0 + r) * Dm + h * DH + q * 4];
        float* dst = &Hs[r * 68 + q * 4];
        dst[0] = v.x; dst[1] = v.y; dst[2] = v.z; dst[3] = v.w;
    }

    const float* Wt[3] = {Wq, Wk, Wv};
    const float* bt[3] = {bq, bk, bv};

    for (int wsel = 0; wsel < 3; wsel++) {
        __syncthreads();
        const float* W = Wt[wsel] + h * DH * DH;
        for (int i = tid; i < 64 * 16; i += 256) {
            int r = i >> 4, q = i & 15;
            float4 v = *(const float4*)&W[r * DH + q * 4];
            float* dst = &Ws[r * 68 + q * 4];
            dst[0] = v.x; dst[1] = v.y; dst[2] = v.z; dst[3] = v.w;
        }
        __syncthreads();

        float c[2][4][4];
        #pragma unroll
        for (int mi = 0; mi < 2; mi++)
            #pragma unroll
            for (int ni = 0; ni < 4; ni++)
                #pragma unroll
                for (int q = 0; q < 4; q++) c[mi][ni][q] = 0.f;

        #pragma unroll
        for (int k0 = 0; k0 < 64; k0 += 8) {
            unsigned a[2][4], bb[4][2];
            #pragma unroll
            for (int mi = 0; mi < 2; mi++) {
                int rb = warpM * 32 + mi * 16 + (lane >> 2);
                a[mi][0] = f2tf(Hs[rb * 68 + k0 + (lane & 3)]);
                a[mi][1] = f2tf(Hs[(rb + 8) * 68 + k0 + (lane & 3)]);
                a[mi][2] = f2tf(Hs[rb * 68 + k0 + 4 + (lane & 3)]);
                a[mi][3] = f2tf(Hs[(rb + 8) * 68 + k0 + 4 + (lane & 3)]);
            }
            #pragma unroll
            for (int ni = 0; ni < 4; ni++) {
                int nb = warpN * 32 + ni * 8 + (lane >> 2);
                bb[ni][0] = f2tf(Ws[nb * 68 + k0 + (lane & 3)]);
                bb[ni][1] = f2tf(Ws[nb * 68 + k0 + 4 + (lane & 3)]);
            }
            #pragma unroll
            for (int mi = 0; mi < 2; mi++)
                #pragma unroll
                for (int ni = 0; ni < 4; ni++)
                    mma_tf32(c[mi][ni], a[mi][0], a[mi][1], a[mi][2], a[mi][3],
                             bb[ni][0], bb[ni][1]);
        }

        const float* bias = bt[wsel] + h * DH;
        size_t obase = ((size_t)(b * NH + h) * Sq + s) * DH;
        if (wsel < 2) {
            __half* O = (wsel == 0 ? g_Q : g_K) + obase;
            #pragma unroll
            for (int mi = 0; mi < 2; mi++)
                #pragma unroll
                for (int ni = 0; ni < 4; ni++) {
                    int r  = warpM * 32 + mi * 16 + (lane >> 2);
                    int cN = warpN * 32 + ni * 8 + (lane & 3) * 2;
                    float b0v = bias[cN], b1v = bias[cN + 1];
                    *(__half2*)&O[(size_t)r * DH + cN] =
                        __floats2half2_rn(c[mi][ni][0] + b0v, c[mi][ni][1] + b1v);
                    *(__half2*)&O[(size_t)(r + 8) * DH + cN] =
                        __floats2half2_rn(c[mi][ni][2] + b0v, c[mi][ni][3] + b1v);
                }
        } else {
            float* O = g_V + obase;
            #pragma unroll
            for (int mi = 0; mi < 2; mi++)
                #pragma unroll
                for (int ni = 0; ni < 4; ni++) {
                    int r  = warpM * 32 + mi * 16 + (lane >> 2);
                    int cN = warpN * 32 + ni * 8 + (lane & 3) * 2;
                    float b0v = bias[cN], b1v = bias[cN + 1];
                    O[(size_t)r * DH + cN]           = c[mi][ni][0] + b0v;
                    O[(size_t)r * DH + cN + 1]       = c[mi][ni][1] + b1v;
                    O[(size_t)(r + 8) * DH + cN]     = c[mi][ni][2] + b0v;
                    O[(size_t)(r + 8) * DH + cN + 1] = c[mi][ni][3] + b1v;
                }
        }
    }
}

// ============================================================================
// K2: attention, fp16 mma + ldmatrix. block = (b, h, 32 query rows), 256 thr.
// scores f32 in smem -> register softmax -> A written f32, normalized P half
// -> P@V fp16 mma. grid (32, B, NH).
// ============================================================================
__global__ void __launch_bounds__(256) attn_kernel(
    const int* __restrict__ mask, float* __restrict__ Aout)
{
    extern __shared__ float sm[];
    float*  ps  = sm;                                   // 32 x 1032 f32
    __half* Ph  = (__half*)(sm + 32 * PS_STRIDE);       // 32 x 1032 half
    __half* Qs  = Ph + 32 * P_STRIDE;                   // 32 x 72
    __half* KVs = Qs + 32 * TS;                         // 128 x 72

    const int tid = threadIdx.x, lane = tid & 31, warp = tid >> 5;
    const int h = blockIdx.z, b = blockIdx.y, s0 = blockIdx.x * 32;
    const int g = lane >> 3, rr = lane & 7;

    const __half* Qg = g_Q + ((size_t)(b * NH + h) * Sq + s0) * DH;
    const __half* Kg = g_K + (size_t)(b * NH + h) * Sq * DH;
    const float*  Vg = g_V + (size_t)(b * NH + h) * Sq * DH;

    // load Q tile 32x64 half
    for (int i = tid; i < 32 * 8; i += 256) {
        int r = i >> 3, q = i & 7;
        *(uint4*)&Qs[r * TS + q * 8] = ((const uint4*)Qg)[r * 8 + q];
    }
    __syncthreads();

    const int warpM = warp >> 2;   // 0..1: 16 rows
    const int warpN = warp & 3;    // 0..3: 32 key cols of 128-tile

    // preload Q fragments (loop-invariant): 4 k16 steps
    unsigned qa[4][4];
    #pragma unroll
    for (int ks = 0; ks < 4; ks++) {
        int row = warpM * 16 + rr + (g & 1) * 8;
        int col = ks * 16 + (g >> 1) * 8;
        ldm_x4(qa[ks], sptr(&Qs[row * TS + col]));
    }

    // ---- Phase A: scores = Q K^T / 8 into smem ----
    for (int kt = 0; kt < 8; kt++) {
        __syncthreads();
        for (int i = tid; i < 128 * 8; i += 256) {
            int r = i >> 3, q = i & 7;
            *(uint4*)&KVs[r * TS + q * 8] =
                ((const uint4*)(Kg + (size_t)(kt * 128 + r) * DH))[q];
        }
        __syncthreads();

        float c[4][4];
        #pragma unroll
        for (int t = 0; t < 4; t++)
            #pragma unroll
            for (int q = 0; q < 4; q++) c[t][q] = 0.f;

        #pragma unroll
        for (int ks = 0; ks < 4; ks++) {
            #pragma unroll
            for (int hn = 0; hn < 2; hn++) {
                int n0 = warpN * 32 + hn * 16;
                int row = n0 + rr + (g >> 1) * 8;
                int col = ks * 16 + (g & 1) * 8;
                unsigned bb[4];
                ldm_x4(bb, sptr(&KVs[row * TS + col]));
                mma_f16(c[hn * 2 + 0], qa[ks], bb[0], bb[1]);
                mma_f16(c[hn * 2 + 1], qa[ks], bb[2], bb[3]);
            }
        }
        int r = warpM * 16 + (lane >> 2);
        #pragma unroll
        for (int t = 0; t < 4; t++) {
            int cN = kt * 128 + warpN * 32 + t * 8 + (lane & 3) * 2;
            ps[r * PS_STRIDE + cN]           = c[t][0] * 0.125f;
            ps[r * PS_STRIDE + cN + 1]       = c[t][1] * 0.125f;
            ps[(r + 8) * PS_STRIDE + cN]     = c[t][2] * 0.125f;
            ps[(r + 8) * PS_STRIDE + cN + 1] = c[t][3] * 0.125f;
        }
    }
    __syncthreads();

    // ---- softmax: warp w owns rows 4w..4w+3; row elems held in registers ----
    #pragma unroll
    for (int ri = 0; ri < 4; ri++) {
        int r = warp * 4 + ri;
        const int* mrow = mask + ((size_t)b * Sq + s0 + r) * Sq;
        float sv[32];
        float mx = NEGV;
        #pragma unroll
        for (int t = 0; t < 32; t++) {
            int j = t * 32 + lane;
            float s = ps[r * PS_STRIDE + j];
            s = (mrow[j] == 0) ? NEGV : s;
            sv[t] = s;
            mx = fmaxf(mx, s);
        }
        #pragma unroll
        for (int o = 16; o; o >>= 1) mx = fmaxf(mx, __shfl_xor_sync(~0u, mx, o));
        float sum = 0.f;
        #pragma unroll
        for (int t = 0; t < 32; t++) {
            float e = __expf(sv[t] - mx);
            sv[t] = e;
            sum += e;
        }
        #pragma unroll
        for (int o = 16; o; o >>= 1) sum += __shfl_xor_sync(~0u, sum, o);
        float inv = 1.0f / sum;
        float* Ar = Aout + (((size_t)h * Bq + b) * Sq + s0 + r) * Sq;
        #pragma unroll
        for (int t = 0; t < 32; t++) {
            int j = t * 32 + lane;
            float a = sv[t] * inv;
            Ar[j] = a;
            Ph[r * P_STRIDE + j] = __float2half_rn(a);
        }
    }
    __syncthreads();

    // ---- Phase B: heads(32x64) = P(32x1024, half) @ V(1024x64) ----
    float c2[2][4];
    #pragma unroll
    for (int t = 0; t < 2; t++)
        #pragma unroll
        for (int q = 0; q < 4; q++) c2[t][q] = 0.f;

    const int n0 = warpN * 16;
    for (int kt = 0; kt < 8; kt++) {
        __syncthreads();
        // V tile f32 -> half
        for (int i = tid; i < 128 * 16; i += 256) {
            int r = i >> 4, q = i & 15;
            float4 v = *(const float4*)&Vg[(size_t)(kt * 128 + r) * DH + q * 4];
            __half2* dst = (__half2*)&KVs[r * TS + q * 4];
            dst[0] = __floats2half2_rn(v.x, v.y);
            dst[1] = __floats2half2_rn(v.z, v.w);
        }
        __syncthreads();

        #pragma unroll
        for (int k0 = 0; k0 < 128; k0 += 16) {
            // A fragment from Ph
            unsigned a[4];
            int arow = warpM * 16 + rr + (g & 1) * 8;
            int acol = kt * 128 + k0 + (g >> 1) * 8;
            ldm_x4(a, sptr(&Ph[arow * P_STRIDE + acol]));
            // B fragment (trans) from V tile [k][n]
            unsigned bb[4];
            int brow = k0 + rr + (g & 1) * 8;
            int bcol = n0 + (g >> 1) * 8;
            ldm_x4_t(bb, sptr(&KVs[brow * TS + bcol]));
            mma_f16(c2[0], a, bb[0], bb[1]);
            mma_f16(c2[1], a, bb[2], bb[3]);
        }
    }

    {
        int r = warpM * 16 + (lane >> 2);
        size_t base = ((size_t)(b * Sq + s0)) * Dm + h * DH;
        #pragma unroll
        for (int t = 0; t < 2; t++) {
            int cN = n0 + t * 8 + (lane & 3) * 2;
            g_heads[base + (size_t)r * Dm + cN]           = c2[t][0];
            g_heads[base + (size_t)r * Dm + cN + 1]       = c2[t][1];
            g_heads[base + (size_t)(r + 8) * Dm + cN]     = c2[t][2];
            g_heads[base + (size_t)(r + 8) * Dm + cN + 1] = c2[t][3];
        }
    }
}

// ============================================================================
// K3: output = heads(8192x1024) @ Wo^T + bo. fp16 mma, tile 128x128, 256 thr.
// grid (64, 8)
// ============================================================================
__global__ void __launch_bounds__(256) out_kernel(
    const float* __restrict__ Wo, const float* __restrict__ bo,
    float* __restrict__ out)
{
    extern __shared__ __half hsm[];
    __half* As = hsm;              // 128 x 72
    __half* Bs = hsm + 128 * TS;   // 128 x 72

    const int tid = threadIdx.x, lane = tid & 31, warp = tid >> 5;
    const int g = lane >> 3, rr = lane & 7;
    const int warpM = warp >> 2;   // 0..1: 64 rows
    const int warpN = warp & 3;    // 0..3: 32 cols
    const int r0 = blockIdx.x * 128, n0 = blockIdx.y * 128;

    float c[4][4][4];
    #pragma unroll
    for (int mi = 0; mi < 4; mi++)
        #pragma unroll
        for (int nt = 0; nt < 4; nt++)
            #pragma unroll
            for (int q = 0; q < 4; q++) c[mi][nt][q] = 0.f;

    for (int kt = 0; kt < 16; kt++) {
        __syncthreads();
        for (int i = tid; i < 128 * 16; i += 256) {
            int r = i >> 4, q = i & 15;
            float4 v = *(const float4*)&g_heads[(size_t)(r0 + r) * Dm + kt * 64 + q * 4];
            __half2* dst = (__half2*)&As[r * TS + q * 4];
            dst[0] = __floats2half2_rn(v.x, v.y);
            dst[1] = __floats2half2_rn(v.z, v.w);
        }
        for (int i = tid; i < 128 * 16; i += 256) {
            int r = i >> 4, q = i & 15;
            float4 v = *(const float4*)&Wo[(size_t)(n0 + r) * Dm + kt * 64 + q * 4];
            __half2* dst = (__half2*)&Bs[r * TS + q * 4];
            dst[0] = __floats2half2_rn(v.x, v.y);
            dst[1] = __floats2half2_rn(v.z, v.w);
        }
        __syncthreads();

        #pragma unroll
        for (int ks = 0; ks < 4; ks++) {
            int k0 = ks * 16;
            unsigned a[4][4];
            #pragma unroll
            for (int mi = 0; mi < 4; mi++) {
                int row = warpM * 64 + mi * 16 + rr + (g & 1) * 8;
                int col = k0 + (g >> 1) * 8;
                ldm_x4(a[mi], sptr(&As[row * TS + col]));
            }
            unsigned bb[2][4];
            #pragma unroll
            for (int hn = 0; hn < 2; hn++) {
                int row = warpN * 32 + hn * 16 + rr + (g >> 1) * 8;
                int col = k0 + (g & 1) * 8;
                ldm_x4(bb[hn], sptr(&Bs[row * TS + col]));
            }
            #pragma unroll
            for (int mi = 0; mi < 4; mi++) {
                mma_f16(c[mi][0], a[mi], bb[0][0], bb[0][1]);
                mma_f16(c[mi][1], a[mi], bb[0][2], bb[0][3]);
                mma_f16(c[mi][2], a[mi], bb[1][0], bb[1][1]);
                mma_f16(c[mi][3], a[mi], bb[1][2], bb[1][3]);
            }
        }
    }

    #pragma unroll
    for (int mi = 0; mi < 4; mi++) {
        #pragma unroll
        for (int nt = 0; nt < 4; nt++) {
            int r  = r0 + warpM * 64 + mi * 16 + (lane >> 2);
            int cN = n0 + warpN * 32 + nt * 8 + (lane & 3) * 2;
            float b0v = bo[cN], b1v = bo[cN + 1];
            out[(size_t)r * Dm + cN]           = c[mi][nt][0] + b0v;
            out[(size_t)r * Dm + cN + 1]       = c[mi][nt][1] + b1v;
            out[(size_t)(r + 8) * Dm + cN]     = c[mi][nt][2] + b0v;
            out[(size_t)(r + 8) * Dm + cN + 1] = c[mi][nt][3] + b1v;
        }
    }
}

// ============================================================================
extern "C" void kernel_launch(void* const* d_in, const int* in_sizes, int n_in,
                              void* d_out, int out_size)
{
    const float* H    = (const float*)d_in[0];
    const int*   mask = (const int*)  d_in[1];
    const float* Wq   = (const float*)d_in[2];
    const float* bq   = (const float*)d_in[3];
    const float* Wk   = (const float*)d_in[4];
    const float* bk   = (const float*)d_in[5];
    const float* Wv   = (const float*)d_in[6];
    const float* bv   = (const float*)d_in[7];
    const float* Wo   = (const float*)d_in[8];
    const float* bo   = (const float*)d_in[9];

    float* out  = (float*)d_out;
    float* Aout = out + (size_t)Bq * Sq * Dm;

    const int smem1 = (128 + 64) * 68 * sizeof(float);                 // 52224
    const int smem2 = 32 * PS_STRIDE * 4 + 32 * P_STRIDE * 2
                    + 32 * TS * 2 + 128 * TS * 2;                      // 221184
    const int smem3 = 2 * 128 * TS * sizeof(__half);                   // 36864

    cudaFuncSetAttribute(qkv_kernel,  cudaFuncAttributeMaxDynamicSharedMemorySize, smem1);
    cudaFuncSetAttribute(attn_kernel, cudaFuncAttributeMaxDynamicSharedMemorySize, smem2);
    cudaFuncSetAttribute(out_kernel,  cudaFuncAttributeMaxDynamicSharedMemorySize, smem3);

    qkv_kernel<<<dim3(64, NH), 256, smem1>>>(H, Wq, bq, Wk, bk, Wv, bv);
    attn_kernel<<<dim3(32, Bq, NH), 256, smem2>>>(mask, Aout);
    out_kernel<<<dim3(64, 8), 256, smem3>>>(Wo, bo, out);
}

// round 3
// speedup vs baseline: 3.1098x; 2.7723x over previous
#include <cuda_runtime.h>
#include <cuda_fp16.h>

#define Bq 8
#define Sq 1024
#define Dm 1024
#define NH 16
#define DH 64
#define NEGV (-1e9f)

#define PSH 1032   // half score/P row stride (2064B -> +4 banks/row, LDSM conflict-free)
#define TS  72     // half tile row stride (144B -> +4 banks/row)

// ---- scratch (device globals: allocation-free rule) ----
__device__ __half g_Q[(size_t)Bq*NH*Sq*DH];
__device__ __half g_K[(size_t)Bq*NH*Sq*DH];
__device__ __half g_V[(size_t)Bq*NH*Sq*DH];
__device__ __half g_heads[(size_t)Bq*Sq*Dm];
__device__ __half g_Woh[(size_t)Dm*Dm];

// ---- helpers ----
__device__ __forceinline__ unsigned f2tf(float f) {
    unsigned r;
    asm("cvt.rna.tf32.f32 %0, %1;" : "=r"(r) : "f"(f));
    return r;
}
__device__ __forceinline__ void mma_tf32(float c[4],
                                         unsigned a0, unsigned a1, unsigned a2, unsigned a3,
                                         unsigned b0, unsigned b1) {
    asm volatile(
        "mma.sync.aligned.m16n8k8.row.col.f32.tf32.tf32.f32 "
        "{%0,%1,%2,%3}, {%4,%5,%6,%7}, {%8,%9}, {%0,%1,%2,%3};"
        : "+f"(c[0]), "+f"(c[1]), "+f"(c[2]), "+f"(c[3])
        : "r"(a0), "r"(a1), "r"(a2), "r"(a3), "r"(b0), "r"(b1));
}
__device__ __forceinline__ void mma_f16(float c[4], const unsigned a[4],
                                        unsigned b0, unsigned b1) {
    asm volatile(
        "mma.sync.aligned.m16n8k16.row.col.f32.f16.f16.f32 "
        "{%0,%1,%2,%3}, {%4,%5,%6,%7}, {%8,%9}, {%0,%1,%2,%3};"
        : "+f"(c[0]), "+f"(c[1]), "+f"(c[2]), "+f"(c[3])
        : "r"(a[0]), "r"(a[1]), "r"(a[2]), "r"(a[3]), "r"(b0), "r"(b1));
}
__device__ __forceinline__ unsigned sptr(const void* p) {
    return (unsigned)__cvta_generic_to_shared(p);
}
__device__ __forceinline__ void ldm_x4(unsigned r[4], unsigned addr) {
    asm volatile("ldmatrix.sync.aligned.m8n8.x4.shared.b16 {%0,%1,%2,%3}, [%4];"
                 : "=r"(r[0]), "=r"(r[1]), "=r"(r[2]), "=r"(r[3]) : "r"(addr));
}
__device__ __forceinline__ void ldm_x4_t(unsigned r[4], unsigned addr) {
    asm volatile("ldmatrix.sync.aligned.m8n8.x4.trans.shared.b16 {%0,%1,%2,%3}, [%4];"
                 : "=r"(r[0]), "=r"(r[1]), "=r"(r[2]), "=r"(r[3]) : "r"(addr));
}
__device__ __forceinline__ void cpa16(unsigned dst, const void* src) {
    asm volatile("cp.async.cg.shared.global [%0], [%1], 16;" :: "r"(dst), "l"(src));
}
#define CPA_COMMIT() asm volatile("cp.async.commit_group;")
#define CPA_WAIT1()  asm volatile("cp.async.wait_group 1;")
#define CPA_WAIT0()  asm volatile("cp.async.wait_group 0;")

// ============================================================================
// K0: Wo f32 -> half (once)
// ============================================================================
__global__ void wconv_kernel(const float* __restrict__ Wo) {
    int i = (blockIdx.x * 256 + threadIdx.x) * 4;
    float4 v = *(const float4*)&Wo[i];
    __half2* dst = (__half2*)&g_Woh[i];
    dst[0] = __floats2half2_rn(v.x, v.y);
    dst[1] = __floats2half2_rn(v.z, v.w);
}

// ============================================================================
// K1: fused QKV projection (tf32), all outputs stored half. grid (64, NH)
// ============================================================================
__global__ void __launch_bounds__(256) qkv_kernel(
    const float* __restrict__ H,
    const float* __restrict__ Wq, const float* __restrict__ bq,
    const float* __restrict__ Wk, const float* __restrict__ bk,
    const float* __restrict__ Wv, const float* __restrict__ bv)
{
    extern __shared__ float sm[];
    float* Hs = sm;              // 128 x 68
    float* Ws = sm + 128 * 68;   // 64 x 68

    const int tid  = threadIdx.x;
    const int lane = tid & 31;
    const int warp = tid >> 5;
    const int warpM = warp >> 1;
    const int warpN = warp & 1;
    const int h    = blockIdx.y;
    const int row0 = blockIdx.x * 128;
    const int b    = row0 >> 10;
    const int s    = row0 & 1023;

    for (int i = tid; i < 128 * 16; i += 256) {
        int r = i >> 4, q = i & 15;
        float4 v = *(const float4*)&H[(size_t)(row0 + r) * Dm + h * DH + q * 4];
        float* dst = &Hs[r * 68 + q * 4];
        dst[0] = v.x; dst[1] = v.y; dst[2] = v.z; dst[3] = v.w;
    }

    const float* Wt[3] = {Wq, Wk, Wv};
    const float* bt[3] = {bq, bk, bv};
    __half*      Ot[3] = {g_Q, g_K, g_V};

    for (int wsel = 0; wsel < 3; wsel++) {
        __syncthreads();
        const float* W = Wt[wsel] + h * DH * DH;
        for (int i = tid; i < 64 * 16; i += 256) {
            int r = i >> 4, q = i & 15;
            float4 v = *(const float4*)&W[r * DH + q * 4];
            float* dst = &Ws[r * 68 + q * 4];
            dst[0] = v.x; dst[1] = v.y; dst[2] = v.z; dst[3] = v.w;
        }
        __syncthreads();

        float c[2][4][4];
        #pragma unroll
        for (int mi = 0; mi < 2; mi++)
            #pragma unroll
            for (int ni = 0; ni < 4; ni++)
                #pragma unroll
                for (int q = 0; q < 4; q++) c[mi][ni][q] = 0.f;

        #pragma unroll
        for (int k0 = 0; k0 < 64; k0 += 8) {
            unsigned a[2][4], bb[4][2];
            #pragma unroll
            for (int mi = 0; mi < 2; mi++) {
                int rb = warpM * 32 + mi * 16 + (lane >> 2);
                a[mi][0] = f2tf(Hs[rb * 68 + k0 + (lane & 3)]);
                a[mi][1] = f2tf(Hs[(rb + 8) * 68 + k0 + (lane & 3)]);
                a[mi][2] = f2tf(Hs[rb * 68 + k0 + 4 + (lane & 3)]);
                a[mi][3] = f2tf(Hs[(rb + 8) * 68 + k0 + 4 + (lane & 3)]);
            }
            #pragma unroll
            for (int ni = 0; ni < 4; ni++) {
                int nb = warpN * 32 + ni * 8 + (lane >> 2);
                bb[ni][0] = f2tf(Ws[nb * 68 + k0 + (lane & 3)]);
                bb[ni][1] = f2tf(Ws[nb * 68 + k0 + 4 + (lane & 3)]);
            }
            #pragma unroll
            for (int mi = 0; mi < 2; mi++)
                #pragma unroll
                for (int ni = 0; ni < 4; ni++)
                    mma_tf32(c[mi][ni], a[mi][0], a[mi][1], a[mi][2], a[mi][3],
                             bb[ni][0], bb[ni][1]);
        }

        const float* bias = bt[wsel] + h * DH;
        __half* O = Ot[wsel] + ((size_t)(b * NH + h) * Sq + s) * DH;
        #pragma unroll
        for (int mi = 0; mi < 2; mi++)
            #pragma unroll
            for (int ni = 0; ni < 4; ni++) {
                int r  = warpM * 32 + mi * 16 + (lane >> 2);
                int cN = warpN * 32 + ni * 8 + (lane & 3) * 2;
                float b0v = bias[cN], b1v = bias[cN + 1];
                *(__half2*)&O[(size_t)r * DH + cN] =
                    __floats2half2_rn(c[mi][ni][0] + b0v, c[mi][ni][1] + b1v);
                *(__half2*)&O[(size_t)(r + 8) * DH + cN] =
                    __floats2half2_rn(c[mi][ni][2] + b0v, c[mi][ni][3] + b1v);
            }
    }
}

// ============================================================================
// K2: attention. grid (NH, 32, Bq) -- h fastest => mask slice shared in L2.
// half scores in smem (softmax in f32), A written f32 streaming, P in place.
// cp.async double-buffered K/V tiles. 256 thr.
// ============================================================================
__global__ void __launch_bounds__(256) attn_kernel(
    const int* __restrict__ mask, float* __restrict__ Aout)
{
    extern __shared__ __half hsm[];
    __half* psh = hsm;                 // 32 x 1032 half: scores -> P
    __half* Qs  = psh + 32 * PSH;      // 32 x 72
    __half* KVs = Qs + 32 * TS;        // 2 x 128 x 72 (double buffer)

    const int tid = threadIdx.x, lane = tid & 31, warp = tid >> 5;
    const int h = blockIdx.x, b = blockIdx.z, s0 = blockIdx.y * 32;
    const int g = lane >> 3, rr = lane & 7;

    const __half* Qg = g_Q + ((size_t)(b * NH + h) * Sq + s0) * DH;
    const __half* Kg = g_K + (size_t)(b * NH + h) * Sq * DH;
    const __half* Vg = g_V + (size_t)(b * NH + h) * Sq * DH;

    // load Q tile 32x64
    for (int i = tid; i < 32 * 8; i += 256) {
        int r = i >> 3, q = i & 7;
        *(uint4*)&Qs[r * TS + q * 8] = ((const uint4*)Qg)[r * 8 + q];
    }

    const int warpM = warp >> 2;   // 0..1: 16 rows
    const int warpN = warp & 3;    // 0..3: 32 cols of 128-wide tile

    // issue K tile 0
    {
        for (int i = tid; i < 128 * 8; i += 256) {
            int r = i >> 3, q = i & 7;
            cpa16(sptr(&KVs[r * TS + q * 8]), Kg + (size_t)r * DH + q * 8);
        }
        CPA_COMMIT();
    }
    __syncthreads();

    // preload Q fragments (loop-invariant)
    unsigned qa[4][4];
    #pragma unroll
    for (int ks = 0; ks < 4; ks++) {
        int row = warpM * 16 + rr + (g & 1) * 8;
        int col = ks * 16 + (g >> 1) * 8;
        ldm_x4(qa[ks], sptr(&Qs[row * TS + col]));
    }

    // ---- Phase A: scores = Q K^T / 8 -> half smem ----
    for (int kt = 0; kt < 8; kt++) {
        if (kt < 7) {
            __half* dst = KVs + ((kt + 1) & 1) * 128 * TS;
            const __half* src = Kg + (size_t)(kt + 1) * 128 * DH;
            for (int i = tid; i < 128 * 8; i += 256) {
                int r = i >> 3, q = i & 7;
                cpa16(sptr(&dst[r * TS + q * 8]), src + (size_t)r * DH + q * 8);
            }
            CPA_COMMIT();
            CPA_WAIT1();
        } else {
            CPA_WAIT0();
        }
        __syncthreads();
        const __half* Kt = KVs + (kt & 1) * 128 * TS;

        float c[4][4];
        #pragma unroll
        for (int t = 0; t < 4; t++)
            #pragma unroll
            for (int q = 0; q < 4; q++) c[t][q] = 0.f;

        #pragma unroll
        for (int ks = 0; ks < 4; ks++) {
            #pragma unroll
            for (int hn = 0; hn < 2; hn++) {
                int n0 = warpN * 32 + hn * 16;
                int row = n0 + rr + (g >> 1) * 8;
                int col = ks * 16 + (g & 1) * 8;
                unsigned bb[4];
                ldm_x4(bb, sptr(&Kt[row * TS + col]));
                mma_f16(c[hn * 2 + 0], qa[ks], bb[0], bb[1]);
                mma_f16(c[hn * 2 + 1], qa[ks], bb[2], bb[3]);
            }
        }
        int r = warpM * 16 + (lane >> 2);
        #pragma unroll
        for (int t = 0; t < 4; t++) {
            int cN = kt * 128 + warpN * 32 + t * 8 + (lane & 3) * 2;
            *(__half2*)&psh[r * PSH + cN] =
                __floats2half2_rn(c[t][0] * 0.125f, c[t][1] * 0.125f);
            *(__half2*)&psh[(r + 8) * PSH + cN] =
                __floats2half2_rn(c[t][2] * 0.125f, c[t][3] * 0.125f);
        }
        __syncthreads();
    }

    // ---- softmax: warp w owns rows 4w..4w+3; elems in registers ----
    #pragma unroll
    for (int ri = 0; ri < 4; ri++) {
        int r = warp * 4 + ri;
        const int* mrow = mask + ((size_t)b * Sq + s0 + r) * Sq;
        float sv[32];
        float mx = NEGV;
        #pragma unroll
        for (int t = 0; t < 32; t++) {
            int j = t * 32 + lane;
            float s = __half2float(psh[r * PSH + j]);
            s = (mrow[j] == 0) ? NEGV : s;
            sv[t] = s;
            mx = fmaxf(mx, s);
        }
        #pragma unroll
        for (int o = 16; o; o >>= 1) mx = fmaxf(mx, __shfl_xor_sync(~0u, mx, o));
        float sum = 0.f;
        #pragma unroll
        for (int t = 0; t < 32; t++) {
            float e = __expf(sv[t] - mx);
            sv[t] = e;
            sum += e;
        }
        #pragma unroll
        for (int o = 16; o; o >>= 1) sum += __shfl_xor_sync(~0u, sum, o);
        float inv = 1.0f / sum;
        float* Ar = Aout + (((size_t)h * Bq + b) * Sq + s0 + r) * Sq;
        #pragma unroll
        for (int t = 0; t < 32; t++) {
            int j = t * 32 + lane;
            float a = sv[t] * inv;
            __stcs(&Ar[j], a);                       // streaming: keep L2 for K/V/mask
            psh[r * PSH + j] = __float2half_rn(a);   // normalized P in place
        }
    }

    // issue V tile 0
    {
        for (int i = tid; i < 128 * 8; i += 256) {
            int r = i >> 3, q = i & 7;
            cpa16(sptr(&KVs[r * TS + q * 8]), Vg + (size_t)r * DH + q * 8);
        }
        CPA_COMMIT();
    }

    // ---- Phase B: heads(32x64) = P @ V ----
    float c2[2][4];
    #pragma unroll
    for (int t = 0; t < 2; t++)
        #pragma unroll
        for (int q = 0; q < 4; q++) c2[t][q] = 0.f;

    const int n0 = warpN * 16;
    for (int kt = 0; kt < 8; kt++) {
        if (kt < 7) {
            __half* dst = KVs + ((kt + 1) & 1) * 128 * TS;
            const __half* src = Vg + (size_t)(kt + 1) * 128 * DH;
            for (int i = tid; i < 128 * 8; i += 256) {
                int r = i >> 3, q = i & 7;
                cpa16(sptr(&dst[r * TS + q * 8]), src + (size_t)r * DH + q * 8);
            }
            CPA_COMMIT();
            CPA_WAIT1();
        } else {
            CPA_WAIT0();
        }
        __syncthreads();
        const __half* Vt = KVs + (kt & 1) * 128 * TS;

        #pragma unroll
        for (int k0 = 0; k0 < 128; k0 += 16) {
            unsigned a[4];
            int arow = warpM * 16 + rr + (g & 1) * 8;
            int acol = kt * 128 + k0 + (g >> 1) * 8;
            ldm_x4(a, sptr(&psh[arow * PSH + acol]));
            unsigned bb[4];
            int brow = k0 + rr + (g & 1) * 8;
            int bcol = n0 + (g >> 1) * 8;
            ldm_x4_t(bb, sptr(&Vt[brow * TS + bcol]));
            mma_f16(c2[0], a, bb[0], bb[1]);
            mma_f16(c2[1], a, bb[2], bb[3]);
        }
        __syncthreads();
    }

    {
        int r = warpM * 16 + (lane >> 2);
        size_t base = ((size_t)(b * Sq + s0)) * Dm + h * DH;
        #pragma unroll
        for (int t = 0; t < 2; t++) {
            int cN = n0 + t * 8 + (lane & 3) * 2;
            *(__half2*)&g_heads[base + (size_t)r * Dm + cN] =
                __floats2half2_rn(c2[t][0], c2[t][1]);
            *(__half2*)&g_heads[base + (size_t)(r + 8) * Dm + cN] =
                __floats2half2_rn(c2[t][2], c2[t][3]);
        }
    }
}

// ============================================================================
// K3: out = heads @ Woh^T + bo. fp16 mma, tile 128x128, cp.async 2-stage.
// grid (64, 8), 256 thr.
// ============================================================================
__global__ void __launch_bounds__(256) out_kernel(
    const float* __restrict__ bo, float* __restrict__ out)
{
    extern __shared__ __half hsm[];
    __half* As = hsm;                  // 2 x 128 x 72
    __half* Bs = hsm + 2 * 128 * TS;   // 2 x 128 x 72

    const int tid = threadIdx.x, lane = tid & 31, warp = tid >> 5;
    const int g = lane >> 3, rr = lane & 7;
    const int warpM = warp >> 2;   // 0..1: 64 rows
    const int warpN = warp & 3;    // 0..3: 32 cols
    const int r0 = blockIdx.x * 128, n0 = blockIdx.y * 128;

    auto issue = [&](int kt, int buf) {
        __half* ad = As + buf * 128 * TS;
        __half* bd = Bs + buf * 128 * TS;
        const __half* as = g_heads + (size_t)r0 * Dm + kt * 64;
        const __half* bs = g_Woh   + (size_t)n0 * Dm + kt * 64;
        for (int i = tid; i < 128 * 8; i += 256) {
            int r = i >> 3, q = i & 7;
            cpa16(sptr(&ad[r * TS + q * 8]), as + (size_t)r * Dm + q * 8);
        }
        for (int i = tid; i < 128 * 8; i += 256) {
            int r = i >> 3, q = i & 7;
            cpa16(sptr(&bd[r * TS + q * 8]), bs + (size_t)r * Dm + q * 8);
        }
        CPA_COMMIT();
    };

    float c[4][4][4];
    #pragma unroll
    for (int mi = 0; mi < 4; mi++)
        #pragma unroll
        for (int nt = 0; nt < 4; nt++)
            #pragma unroll
            for (int q = 0; q < 4; q++) c[mi][nt][q] = 0.f;

    issue(0, 0);

    for (int kt = 0; kt < 16; kt++) {
        if (kt < 15) { issue(kt + 1, (kt + 1) & 1); CPA_WAIT1(); }
        else         { CPA_WAIT0(); }
        __syncthreads();
        const __half* At = As + (kt & 1) * 128 * TS;
        const __half* Bt = Bs + (kt & 1) * 128 * TS;

        #pragma unroll
        for (int ks = 0; ks < 4; ks++) {
            int k0 = ks * 16;
            unsigned a[4][4];
            #pragma unroll
            for (int mi = 0; mi < 4; mi++) {
                int row = warpM * 64 + mi * 16 + rr + (g & 1) * 8;
                int col = k0 + (g >> 1) * 8;
                ldm_x4(a[mi], sptr(&At[row * TS + col]));
            }
            unsigned bb[2][4];
            #pragma unroll
            for (int hn = 0; hn < 2; hn++) {
                int row = warpN * 32 + hn * 16 + rr + (g >> 1) * 8;
                int col = k0 + (g & 1) * 8;
                ldm_x4(bb[hn], sptr(&Bt[row * TS + col]));
            }
            #pragma unroll
            for (int mi = 0; mi < 4; mi++) {
                mma_f16(c[mi][0], a[mi], bb[0][0], bb[0][1]);
                mma_f16(c[mi][1], a[mi], bb[0][2], bb[0][3]);
                mma_f16(c[mi][2], a[mi], bb[1][0], bb[1][1]);
                mma_f16(c[mi][3], a[mi], bb[1][2], bb[1][3]);
            }
        }
        __syncthreads();
    }

    #pragma unroll
    for (int mi = 0; mi < 4; mi++) {
        #pragma unroll
        for (int nt = 0; nt < 4; nt++) {
            int r  = r0 + warpM * 64 + mi * 16 + (lane >> 2);
            int cN = n0 + warpN * 32 + nt * 8 + (lane & 3) * 2;
            float b0v = bo[cN], b1v = bo[cN + 1];
            out[(size_t)r * Dm + cN]           = c[mi][nt][0] + b0v;
            out[(size_t)r * Dm + cN + 1]       = c[mi][nt][1] + b1v;
            out[(size_t)(r + 8) * Dm + cN]     = c[mi][nt][2] + b0v;
            out[(size_t)(r + 8) * Dm + cN + 1] = c[mi][nt][3] + b1v;
        }
    }
}

// ============================================================================
extern "C" void kernel_launch(void* const* d_in, const int* in_sizes, int n_in,
                              void* d_out, int out_size)
{
    const float* H    = (const float*)d_in[0];
    const int*   mask = (const int*)  d_in[1];
    const float* Wq   = (const float*)d_in[2];
    const float* bq   = (const float*)d_in[3];
    const float* Wk   = (const float*)d_in[4];
    const float* bk   = (const float*)d_in[5];
    const float* Wv   = (const float*)d_in[6];
    const float* bv   = (const float*)d_in[7];
    const float* Wo   = (const float*)d_in[8];
    const float* bo   = (const float*)d_in[9];

    float* out  = (float*)d_out;
    float* Aout = out + (size_t)Bq * Sq * Dm;

    const int smem1 = (128 + 64) * 68 * sizeof(float);                     // 52224
    const int smem2 = (32 * PSH + 32 * TS + 2 * 128 * TS) * sizeof(__half); // 107520
    const int smem3 = 4 * 128 * TS * sizeof(__half);                        // 73728

    cudaFuncSetAttribute(qkv_kernel,  cudaFuncAttributeMaxDynamicSharedMemorySize, smem1);
    cudaFuncSetAttribute(attn_kernel, cudaFuncAttributeMaxDynamicSharedMemorySize, smem2);
    cudaFuncSetAttribute(out_kernel,  cudaFuncAttributeMaxDynamicSharedMemorySize, smem3);

    wconv_kernel<<<1024, 256>>>(Wo);
    qkv_kernel<<<dim3(64, NH), 256, smem1>>>(H, Wq, bq, Wk, bk, Wv, bv);
    attn_kernel<<<dim3(NH, 32, Bq), 256, smem2>>>(mask, Aout);
    out_kernel<<<dim3(64, 8), 256, smem3>>>(bo, out);
}